// round 7
// baseline (speedup 1.0000x reference)
#include <cuda_runtime.h>
#include <cuda_bf16.h>
#include <cstdint>

// Problem dims
#define M_DIM 16384
#define N_DIM 4096
#define K_DIM 256
#define KE    768        // expanded K: X'=[hi|hi|lo], W'=[hi|lo|hi]
#define NQ    31

// GEMM tiling: CTA 256x128, 8 warps in 4(m) x 2(n), warp tile 64x64
#define BM 256
#define BN 128
#define BK 64            // bf16 per chunk = 128 bytes per row
#define NCHUNK (KE / BK) // 12

// bf16-split scratch (device globals: allocation-free scratch)
__device__ __nv_bfloat16 g_Xp[(size_t)M_DIM * KE];   // ~25 MB
__device__ __nv_bfloat16 g_Wp[(size_t)N_DIM * KE];   // ~6 MB

// ---- dynamic smem layout (bytes) ----
#define OFF_A0   0          // 256x64 bf16 = 32768
#define OFF_A1   32768
#define OFF_B0   65536      // 128x64 bf16 = 16384
#define OFF_B1   81920
#define OFF_QS   98304      // 128 cols x 33 f32 = 16896
#define OFF_BB   115200     // 128 f32 = 512
#define SMEM_BYTES 115712

__device__ __forceinline__ uint32_t smem_u32(const void* p) {
    uint32_t a;
    asm("{ .reg .u64 t; cvta.to.shared.u64 t, %1; cvt.u32.u64 %0, t; }" : "=r"(a) : "l"(p));
    return a;
}
__device__ __forceinline__ uint32_t sw128(uint32_t off) {   // SW128 within a tile
    return off ^ ((off >> 3) & 0x70);
}
__device__ __forceinline__ void cp_async16(uint32_t dst, const void* src) {
    asm volatile("cp.async.cg.shared.global [%0], [%1], 16;" :: "r"(dst), "l"(src) : "memory");
}
__device__ __forceinline__ void cp_commit() {
    asm volatile("cp.async.commit_group;" ::: "memory");
}
template <int N>
__device__ __forceinline__ void cp_wait() {
    asm volatile("cp.async.wait_group %0;" :: "n"(N) : "memory");
}
__device__ __forceinline__ void ldmatrix_x4(uint32_t* r, uint32_t addr) {
    asm volatile("ldmatrix.sync.aligned.m8n8.x4.shared.b16 {%0,%1,%2,%3}, [%4];"
                 : "=r"(r[0]), "=r"(r[1]), "=r"(r[2]), "=r"(r[3]) : "r"(addr));
}
__device__ __forceinline__ void mma16816(float* d, const uint32_t* a, const uint32_t* b) {
    asm volatile(
        "mma.sync.aligned.m16n8k16.row.col.f32.bf16.bf16.f32 "
        "{%0,%1,%2,%3}, {%4,%5,%6,%7}, {%8,%9}, {%0,%1,%2,%3};"
        : "+f"(d[0]), "+f"(d[1]), "+f"(d[2]), "+f"(d[3])
        : "r"(a[0]), "r"(a[1]), "r"(a[2]), "r"(a[3]), "r"(b[0]), "r"(b[1]));
}

// ================= kernel 1: fp32 -> bf16 hi/lo expansion =================
__global__ void __launch_bounds__(256)
convert_kernel(const float* __restrict__ X, const float* __restrict__ W)
{
    int i = blockIdx.x * blockDim.x + threadIdx.x;   // covers M_DIM*K_DIM
    {
        float x = X[i];
        __nv_bfloat16 hi = __float2bfloat16(x);
        __nv_bfloat16 lo = __float2bfloat16(x - __bfloat162float(hi));
        int m = i >> 8, k = i & 255;
        size_t base = (size_t)m * KE;
        g_Xp[base + k]       = hi;
        g_Xp[base + 256 + k] = hi;
        g_Xp[base + 512 + k] = lo;
    }
    if (i < N_DIM * K_DIM) {
        float w = W[i];
        __nv_bfloat16 hi = __float2bfloat16(w);
        __nv_bfloat16 lo = __float2bfloat16(w - __bfloat162float(hi));
        int n = i >> 8, k = i & 255;
        size_t base = (size_t)n * KE;
        g_Wp[base + k]       = hi;   // pairs with x_hi -> hi*hi
        g_Wp[base + 256 + k] = lo;   // pairs with x_hi -> hi*lo
        g_Wp[base + 512 + k] = hi;   // pairs with x_lo -> lo*hi
    }
}

// ================= kernel 2: HMMA GEMM + fused epilogue =================
extern __shared__ char smem[];

__global__ void __launch_bounds__(256, 1)
gemm_kernel(const float* __restrict__ bias, const float* __restrict__ Q,
            float* __restrict__ out, float* __restrict__ idxf)
{
    const int tid  = threadIdx.x;
    const int wid  = tid >> 5;
    const int lane = tid & 31;
    const int bm = blockIdx.y * BM;
    const int bn = blockIdx.x * BN;
    const uint32_t sb = smem_u32(smem);

    float* qs = (float*)(smem + OFF_QS);   // [128][33]
    float* bb = (float*)(smem + OFF_BB);   // [128]

    // stage quantiles (stride-33 pad) + bias
    for (int i = tid; i < BN * NQ; i += 256) {
        int n = i / NQ, r = i - n * NQ;
        qs[n * 33 + r] = Q[(size_t)(bn + n) * NQ + r];
    }
    if (tid < BN) bb[tid] = bias[bn + tid];

    // --- cp.async tile loaders ---
    const char* gA = (const char*)(g_Xp + (size_t)bm * KE);
    const char* gB = (const char*)(g_Wp + (size_t)bn * KE);

    auto issue = [&](int c) {
        const int b = c & 1;
        const uint32_t aB = sb + (b ? OFF_A1 : OFF_A0);
        const uint32_t bB = sb + (b ? OFF_B1 : OFF_B0);
        const char* pa = gA + c * 128;
        const char* pb = gB + c * 128;
        #pragma unroll
        for (int t = 0; t < 8; ++t) {          // A: 2048 x 16B
            int i = tid + t * 256; int r = i >> 3, q = i & 7;
            uint32_t d = sw128((uint32_t)(r * 128 + q * 16));
            cp_async16(aB + d, pa + (size_t)r * (KE * 2) + q * 16);
        }
        #pragma unroll
        for (int t = 0; t < 4; ++t) {          // B: 1024 x 16B
            int i = tid + t * 256; int r = i >> 3, q = i & 7;
            uint32_t d = sw128((uint32_t)(r * 128 + q * 16));
            cp_async16(bB + d, pb + (size_t)r * (KE * 2) + q * 16);
        }
        cp_commit();
    };

    // warp layout: 4 (m) x 2 (n); warp tile 64 x 64
    const int wm = wid >> 1;
    const int wn = wid & 1;
    const int g  = lane >> 2;    // group id 0..7
    const int t4 = lane & 3;

    // ldmatrix lane address components (within-tile, before swizzle)
    const int a_row_off = lane & 15;
    const int a_k_off   = (lane >> 4) << 4;
    const int b_row_off = (lane & 7) + ((lane & 16) ? 8 : 0);
    const int b_k_off   = ((lane >> 3) & 1) << 4;

    float acc[4][8][4];
    #pragma unroll
    for (int im = 0; im < 4; im++)
        #pragma unroll
        for (int in = 0; in < 8; in++)
            #pragma unroll
            for (int r = 0; r < 4; r++) acc[im][in][r] = 0.f;

    issue(0);

    for (int c = 0; c < NCHUNK; ++c) {
        if (c + 1 < NCHUNK) { issue(c + 1); cp_wait<1>(); }
        else                { cp_wait<0>(); }
        __syncthreads();

        const int b = c & 1;
        const uint32_t aB = sb + (b ? OFF_A1 : OFF_A0);
        const uint32_t bB = sb + (b ? OFF_B1 : OFF_B0);

        #pragma unroll
        for (int ks = 0; ks < 4; ++ks) {
            const int kb = ks * 32;   // byte offset of k-step (16 bf16 = 32B)
            uint32_t afr[4][4], bfr[4][4];
            #pragma unroll
            for (int im = 0; im < 4; im++) {
                uint32_t off = (uint32_t)((wm * 64 + im * 16 + a_row_off) * 128 + kb + a_k_off);
                ldmatrix_x4(afr[im], aB + sw128(off));
            }
            #pragma unroll
            for (int ib = 0; ib < 4; ib++) {
                uint32_t off = (uint32_t)((wn * 64 + ib * 16 + b_row_off) * 128 + kb + b_k_off);
                ldmatrix_x4(bfr[ib], bB + sw128(off));
            }
            #pragma unroll
            for (int im = 0; im < 4; im++)
                #pragma unroll
                for (int in = 0; in < 8; in++)
                    mma16816(acc[im][in], afr[im], bfr[in >> 1] + (in & 1) * 2);
        }
        __syncthreads();
    }

    // ---- epilogue: bias + searchsorted from registers, float2 stores ----
    #pragma unroll
    for (int in = 0; in < 8; in++) {
        const int col_l = wn * 64 + in * 8 + t4 * 2;       // local col (pair base)
        const float* q0 = qs + col_l * 33;
        const float* q1 = q0 + 33;
        const float bz0 = bb[col_l], bz1 = bb[col_l + 1];
        #pragma unroll
        for (int im = 0; im < 4; im++) {
            #pragma unroll
            for (int half = 0; half < 2; half++) {
                const int row = bm + wm * 64 + im * 16 + g + half * 8;
                const float v0 = acc[im][in][half * 2];
                const float v1 = acc[im][in][half * 2 + 1];
                int p0 = 0, p1 = 0;
                if (q0[15]     < v0) p0 = 16;
                if (p0 + 7 < NQ && q0[p0 + 7] < v0) p0 += 8;
                if (p0 + 3 < NQ && q0[p0 + 3] < v0) p0 += 4;
                if (p0 + 1 < NQ && q0[p0 + 1] < v0) p0 += 2;
                if (p0     < NQ && q0[p0]     < v0) p0 += 1;
                if (q1[15]     < v1) p1 = 16;
                if (p1 + 7 < NQ && q1[p1 + 7] < v1) p1 += 8;
                if (p1 + 3 < NQ && q1[p1 + 3] < v1) p1 += 4;
                if (p1 + 1 < NQ && q1[p1 + 1] < v1) p1 += 2;
                if (p1     < NQ && q1[p1]     < v1) p1 += 1;
                const size_t off = (size_t)row * N_DIM + bn + col_l;
                *(float2*)(out  + off) = make_float2(v0 + bz0, v1 + bz1);
                *(float2*)(idxf + off) = make_float2((float)p0, (float)p1);
            }
        }
    }
}

// ================= launch =================
extern "C" void kernel_launch(void* const* d_in, const int* in_sizes, int n_in,
                              void* d_out, int out_size)
{
    const float* x    = (const float*)d_in[0];  // [16384, 256]
    const float* w    = (const float*)d_in[1];  // [4096, 256]
    const float* bias = (const float*)d_in[2];  // [4096]
    const float* q    = (const float*)d_in[3];  // [4096, 31]

    float* out  = (float*)d_out;
    float* idxf = out + (size_t)M_DIM * N_DIM;

    cudaFuncSetAttribute(gemm_kernel, cudaFuncAttributeMaxDynamicSharedMemorySize, SMEM_BYTES);

    convert_kernel<<<(M_DIM * K_DIM) / 256, 256>>>(x, w);
    dim3 grid(N_DIM / BN, M_DIM / BM);   // (32, 64) = 2048 blocks
    gemm_kernel<<<grid, 256, SMEM_BYTES>>>(bias, q, out, idxf);
}

// round 8
// speedup vs baseline: 1.2265x; 1.2265x over previous
#include <cuda_runtime.h>
#include <cuda_bf16.h>
#include <cstdint>

// Problem dims
#define M_DIM 16384
#define N_DIM 4096
#define K_DIM 256
#define NQ    31

// scratch layout: per row, K split into 8 blocks of 32 elems;
// each block stored as [hi x32 | lo x32]  -> row length 512 bf16 = 1024 B
#define KP    512
#define ROWB  1024       // bytes per scratch row

// GEMM tiling: CTA 128x128, 8 warps 4(m) x 2(n), warp tile 32x64
#define BM 128
#define BN 128
#define NCHUNK 8         // base-K chunks of 32 (each = 128 B/row hi+lo)

__device__ __nv_bfloat16 g_Xp[(size_t)M_DIM * KP];   // 16 MB
__device__ __nv_bfloat16 g_Wp[(size_t)N_DIM * KP];   // 4 MB

// ---- dynamic smem layout (bytes) ----
#define OFF_A0   0          // 128 rows x 128B = 16384
#define OFF_A1   16384
#define OFF_B0   32768
#define OFF_B1   49152
#define OFF_QS   65536      // 128 cols x 33 f32 = 16896
#define OFF_BB   82432      // 128 f32 = 512
#define SMEM_BYTES 82944

__device__ __forceinline__ uint32_t smem_u32(const void* p) {
    uint32_t a;
    asm("{ .reg .u64 t; cvta.to.shared.u64 t, %1; cvt.u32.u64 %0, t; }" : "=r"(a) : "l"(p));
    return a;
}
__device__ __forceinline__ uint32_t sw128(uint32_t off) {
    return off ^ ((off >> 3) & 0x70);
}
__device__ __forceinline__ void cp_async16(uint32_t dst, const void* src) {
    asm volatile("cp.async.cg.shared.global [%0], [%1], 16;" :: "r"(dst), "l"(src) : "memory");
}
__device__ __forceinline__ void cp_commit() {
    asm volatile("cp.async.commit_group;" ::: "memory");
}
template <int N>
__device__ __forceinline__ void cp_wait() {
    asm volatile("cp.async.wait_group %0;" :: "n"(N) : "memory");
}
__device__ __forceinline__ void ldmatrix_x4(uint32_t* r, uint32_t addr) {
    asm volatile("ldmatrix.sync.aligned.m8n8.x4.shared.b16 {%0,%1,%2,%3}, [%4];"
                 : "=r"(r[0]), "=r"(r[1]), "=r"(r[2]), "=r"(r[3]) : "r"(addr));
}
__device__ __forceinline__ void ldmatrix_x2(uint32_t* r, uint32_t addr) {
    asm volatile("ldmatrix.sync.aligned.m8n8.x2.shared.b16 {%0,%1}, [%2];"
                 : "=r"(r[0]), "=r"(r[1]) : "r"(addr));
}
__device__ __forceinline__ void mma16816(float* d, const uint32_t* a, const uint32_t* b) {
    asm volatile(
        "mma.sync.aligned.m16n8k16.row.col.f32.bf16.bf16.f32 "
        "{%0,%1,%2,%3}, {%4,%5,%6,%7}, {%8,%9}, {%0,%1,%2,%3};"
        : "+f"(d[0]), "+f"(d[1]), "+f"(d[2]), "+f"(d[3])
        : "r"(a[0]), "r"(a[1]), "r"(a[2]), "r"(a[3]), "r"(b[0]), "r"(b[1]));
}

// ================= kernel 1: fp32 -> bf16 hi/lo (block-interleaved) =========
__global__ void __launch_bounds__(256)
convert_kernel(const float* __restrict__ X, const float* __restrict__ W)
{
    int i = blockIdx.x * blockDim.x + threadIdx.x;   // covers M_DIM*K_DIM
    {
        float x = X[i];
        __nv_bfloat16 hi = __float2bfloat16(x);
        __nv_bfloat16 lo = __float2bfloat16(x - __bfloat162float(hi));
        int m = i >> 8, k = i & 255;
        size_t p = (size_t)m * KP + (k >> 5) * 64 + (k & 31);
        g_Xp[p]      = hi;
        g_Xp[p + 32] = lo;
    }
    if (i < N_DIM * K_DIM) {
        float w = W[i];
        __nv_bfloat16 hi = __float2bfloat16(w);
        __nv_bfloat16 lo = __float2bfloat16(w - __bfloat162float(hi));
        int n = i >> 8, k = i & 255;
        size_t p = (size_t)n * KP + (k >> 5) * 64 + (k & 31);
        g_Wp[p]      = hi;
        g_Wp[p + 32] = lo;
    }
}

// ================= kernel 2: HMMA GEMM + fused epilogue =================
extern __shared__ char smem[];

__global__ void __launch_bounds__(256, 2)
gemm_kernel(const float* __restrict__ bias, const float* __restrict__ Q,
            float* __restrict__ out, float* __restrict__ idxf)
{
    const int tid  = threadIdx.x;
    const int wid  = tid >> 5;
    const int lane = tid & 31;
    const int bm = blockIdx.y * BM;
    const int bn = blockIdx.x * BN;
    const uint32_t sb = smem_u32(smem);

    float* qs = (float*)(smem + OFF_QS);   // [128][33]
    float* bb = (float*)(smem + OFF_BB);   // [128]

    for (int i = tid; i < BN * NQ; i += 256) {
        int n = i / NQ, r = i - n * NQ;
        qs[n * 33 + r] = Q[(size_t)(bn + n) * NQ + r];
    }
    if (tid < BN) bb[tid] = bias[bn + tid];

    const char* gA = (const char*)g_Xp + (size_t)bm * ROWB;
    const char* gB = (const char*)g_Wp + (size_t)bn * ROWB;

    // per stage: A 1024 x 16B + B 1024 x 16B, 256 threads -> 4+4 each
    auto issue = [&](int c) {
        const int b = c & 1;
        const uint32_t aB = sb + (b ? OFF_A1 : OFF_A0);
        const uint32_t bB = sb + (b ? OFF_B1 : OFF_B0);
        const char* pa = gA + c * 128;
        const char* pb = gB + c * 128;
        #pragma unroll
        for (int t = 0; t < 4; ++t) {
            int i = tid + t * 256; int r = i >> 3, q = i & 7;
            uint32_t d = sw128((uint32_t)(r * 128 + q * 16));
            cp_async16(aB + d, pa + (size_t)r * ROWB + q * 16);
        }
        #pragma unroll
        for (int t = 0; t < 4; ++t) {
            int i = tid + t * 256; int r = i >> 3, q = i & 7;
            uint32_t d = sw128((uint32_t)(r * 128 + q * 16));
            cp_async16(bB + d, pb + (size_t)r * ROWB + q * 16);
        }
        cp_commit();
    };

    // warp layout: 4 (m) x 2 (n); warp tile 32 x 64
    const int wm = wid >> 1;
    const int wn = wid & 1;
    const int g  = lane >> 2;
    const int t4 = lane & 3;

    // ldmatrix lane address components (within 128B-row tile, before swizzle)
    const int a_row_off = lane & 15;
    const int a_k_off   = (lane >> 4) << 4;        // 0 or 16 bytes (k split)
    const int b_row_off = (lane & 7) + ((lane & 16) ? 8 : 0);
    const int b_k_off   = ((lane >> 3) & 1) << 4;

    float acc[2][8][4];
    #pragma unroll
    for (int im = 0; im < 2; im++)
        #pragma unroll
        for (int in = 0; in < 8; in++)
            #pragma unroll
            for (int r = 0; r < 4; r++) acc[im][in][r] = 0.f;

    issue(0);

    for (int c = 0; c < NCHUNK; ++c) {
        if (c + 1 < NCHUNK) { issue(c + 1); cp_wait<1>(); }
        else                { cp_wait<0>(); }
        __syncthreads();

        const int b = c & 1;
        const uint32_t aB = sb + (b ? OFF_A1 : OFF_A0);
        const uint32_t bB = sb + (b ? OFF_B1 : OFF_B0);

        // chunk = base-k 32: two k16 steps; hi at row bytes [0,64), lo at [64,128)
        #pragma unroll
        for (int ks = 0; ks < 2; ++ks) {
            const int kb = ks * 32;                 // k16-step byte offset in hi half
            uint32_t ah[2][4], al[2][4];
            #pragma unroll
            for (int im = 0; im < 2; im++) {
                uint32_t rowb = (uint32_t)((wm * 32 + im * 16 + a_row_off) * 128);
                ldmatrix_x4(ah[im], aB + sw128(rowb + kb + a_k_off));
                ldmatrix_x4(al[im], aB + sw128(rowb + 64 + kb + a_k_off));
            }
            #pragma unroll
            for (int nb = 0; nb < 4; nb++) {
                uint32_t bh[4], bl[4];
                uint32_t rowb = (uint32_t)((wn * 64 + nb * 16 + b_row_off) * 128);
                ldmatrix_x4(bh, bB + sw128(rowb + kb + b_k_off));
                ldmatrix_x4(bl, bB + sw128(rowb + 64 + kb + b_k_off));
                #pragma unroll
                for (int im = 0; im < 2; im++) {
                    #pragma unroll
                    for (int half = 0; half < 2; half++) {
                        float* d = acc[im][nb * 2 + half];
                        mma16816(d, ah[im], bh + half * 2);   // hi*hi
                        mma16816(d, ah[im], bl + half * 2);   // hi*lo
                        mma16816(d, al[im], bh + half * 2);   // lo*hi
                    }
                }
            }
        }
        __syncthreads();
    }

    // ---- epilogue: bias + searchsorted from registers, float2 stores ----
    #pragma unroll
    for (int in = 0; in < 8; in++) {
        const int col_l = wn * 64 + in * 8 + t4 * 2;
        const float* q0 = qs + col_l * 33;
        const float* q1 = q0 + 33;
        const float bz0 = bb[col_l], bz1 = bb[col_l + 1];
        #pragma unroll
        for (int im = 0; im < 2; im++) {
            #pragma unroll
            for (int half = 0; half < 2; half++) {
                const int row = bm + wm * 32 + im * 16 + g + half * 8;
                const float v0 = acc[im][in][half * 2];
                const float v1 = acc[im][in][half * 2 + 1];
                int p0 = 0, p1 = 0;
                if (q0[15]     < v0) p0 = 16;
                if (p0 + 7 < NQ && q0[p0 + 7] < v0) p0 += 8;
                if (p0 + 3 < NQ && q0[p0 + 3] < v0) p0 += 4;
                if (p0 + 1 < NQ && q0[p0 + 1] < v0) p0 += 2;
                if (p0     < NQ && q0[p0]     < v0) p0 += 1;
                if (q1[15]     < v1) p1 = 16;
                if (p1 + 7 < NQ && q1[p1 + 7] < v1) p1 += 8;
                if (p1 + 3 < NQ && q1[p1 + 3] < v1) p1 += 4;
                if (p1 + 1 < NQ && q1[p1 + 1] < v1) p1 += 2;
                if (p1     < NQ && q1[p1]     < v1) p1 += 1;
                const size_t off = (size_t)row * N_DIM + bn + col_l;
                *(float2*)(out  + off) = make_float2(v0 + bz0, v1 + bz1);
                *(float2*)(idxf + off) = make_float2((float)p0, (float)p1);
            }
        }
    }
}

// ================= launch =================
extern "C" void kernel_launch(void* const* d_in, const int* in_sizes, int n_in,
                              void* d_out, int out_size)
{
    const float* x    = (const float*)d_in[0];  // [16384, 256]
    const float* w    = (const float*)d_in[1];  // [4096, 256]
    const float* bias = (const float*)d_in[2];  // [4096]
    const float* q    = (const float*)d_in[3];  // [4096, 31]

    float* out  = (float*)d_out;
    float* idxf = out + (size_t)M_DIM * N_DIM;

    cudaFuncSetAttribute(gemm_kernel, cudaFuncAttributeMaxDynamicSharedMemorySize, SMEM_BYTES);

    convert_kernel<<<(M_DIM * K_DIM) / 256, 256>>>(x, w);
    dim3 grid(N_DIM / BN, M_DIM / BM);   // (32, 128) = 4096 blocks
    gemm_kernel<<<grid, 256, SMEM_BYTES>>>(bias, q, out, idxf);
}

// round 9
// speedup vs baseline: 1.2336x; 1.0058x over previous
#include <cuda_runtime.h>
#include <cuda_bf16.h>
#include <cstdint>

// Problem dims
#define M_DIM 16384
#define N_DIM 4096
#define K_DIM 256
#define NQ    31

// scratch layout: per row, K split into 8 blocks of 32 elems;
// each block stored as [hi x32 | lo x32]  -> row length 512 bf16 = 1024 B
#define KP    512
#define ROWB  1024       // bytes per scratch row

// GEMM tiling: CTA 128x128, 8 warps 4(m) x 2(n), warp tile 32x64
#define BM 128
#define BN 128
#define NCHUNK 8         // base-K chunks of 32 (each = 128 B/row hi+lo)
#define NSTAGE 3

__device__ __nv_bfloat16 g_Xp[(size_t)M_DIM * KP];   // 16 MB
__device__ __nv_bfloat16 g_Wp[(size_t)N_DIM * KP];   // 4 MB

// ---- dynamic smem layout (bytes) ----
// 3 stages x (A 16384 + B 16384) = 98304
#define STAGE_BYTES 32768
#define OFF_B_IN_STAGE 16384
#define SMEM_BYTES 98304
// epilogue overlays (main-loop buffers are dead by then):
#define OFF_QS   0          // 128 cols x 33 f32 = 16896
#define OFF_BB   16896      // 128 f32 = 512

__device__ __forceinline__ uint32_t smem_u32(const void* p) {
    uint32_t a;
    asm("{ .reg .u64 t; cvta.to.shared.u64 t, %1; cvt.u32.u64 %0, t; }" : "=r"(a) : "l"(p));
    return a;
}
__device__ __forceinline__ uint32_t sw128(uint32_t off) {
    return off ^ ((off >> 3) & 0x70);
}
__device__ __forceinline__ void cp_async16(uint32_t dst, const void* src) {
    asm volatile("cp.async.cg.shared.global [%0], [%1], 16;" :: "r"(dst), "l"(src) : "memory");
}
__device__ __forceinline__ void cp_commit() {
    asm volatile("cp.async.commit_group;" ::: "memory");
}
template <int N>
__device__ __forceinline__ void cp_wait() {
    asm volatile("cp.async.wait_group %0;" :: "n"(N) : "memory");
}
__device__ __forceinline__ void ldmatrix_x4(uint32_t* r, uint32_t addr) {
    asm volatile("ldmatrix.sync.aligned.m8n8.x4.shared.b16 {%0,%1,%2,%3}, [%4];"
                 : "=r"(r[0]), "=r"(r[1]), "=r"(r[2]), "=r"(r[3]) : "r"(addr));
}
__device__ __forceinline__ void mma16816(float* d, const uint32_t* a, const uint32_t* b) {
    asm volatile(
        "mma.sync.aligned.m16n8k16.row.col.f32.bf16.bf16.f32 "
        "{%0,%1,%2,%3}, {%4,%5,%6,%7}, {%8,%9}, {%0,%1,%2,%3};"
        : "+f"(d[0]), "+f"(d[1]), "+f"(d[2]), "+f"(d[3])
        : "r"(a[0]), "r"(a[1]), "r"(a[2]), "r"(a[3]), "r"(b[0]), "r"(b[1]));
}

// ================= kernel 1: fp32 -> bf16 hi/lo (block-interleaved) =========
__global__ void __launch_bounds__(256)
convert_kernel(const float* __restrict__ X, const float* __restrict__ W)
{
    int i = blockIdx.x * blockDim.x + threadIdx.x;   // covers M_DIM*K_DIM
    {
        float x = X[i];
        __nv_bfloat16 hi = __float2bfloat16(x);
        __nv_bfloat16 lo = __float2bfloat16(x - __bfloat162float(hi));
        int m = i >> 8, k = i & 255;
        size_t p = (size_t)m * KP + (k >> 5) * 64 + (k & 31);
        g_Xp[p]      = hi;
        g_Xp[p + 32] = lo;
    }
    if (i < N_DIM * K_DIM) {
        float w = W[i];
        __nv_bfloat16 hi = __float2bfloat16(w);
        __nv_bfloat16 lo = __float2bfloat16(w - __bfloat162float(hi));
        int n = i >> 8, k = i & 255;
        size_t p = (size_t)n * KP + (k >> 5) * 64 + (k & 31);
        g_Wp[p]      = hi;
        g_Wp[p + 32] = lo;
    }
}

// ================= kernel 2: HMMA GEMM + fused epilogue =================
extern __shared__ char smem[];

__global__ void __launch_bounds__(256, 2)
gemm_kernel(const float* __restrict__ bias, const float* __restrict__ Q,
            float* __restrict__ out, float* __restrict__ idxf)
{
    const int tid  = threadIdx.x;
    const int wid  = tid >> 5;
    const int lane = tid & 31;
    const int bm = blockIdx.y * BM;
    const int bn = blockIdx.x * BN;
    const uint32_t sb = smem_u32(smem);

    const char* gA = (const char*)g_Xp + (size_t)bm * ROWB;
    const char* gB = (const char*)g_Wp + (size_t)bn * ROWB;

    // per stage: A 1024 x 16B + B 1024 x 16B, 256 threads -> 4+4 each
    auto issue = [&](int c) {
        const uint32_t st = sb + (uint32_t)(c % NSTAGE) * STAGE_BYTES;
        const char* pa = gA + c * 128;
        const char* pb = gB + c * 128;
        #pragma unroll
        for (int t = 0; t < 4; ++t) {
            int i = tid + t * 256; int r = i >> 3, q = i & 7;
            uint32_t d = sw128((uint32_t)(r * 128 + q * 16));
            cp_async16(st + d, pa + (size_t)r * ROWB + q * 16);
        }
        #pragma unroll
        for (int t = 0; t < 4; ++t) {
            int i = tid + t * 256; int r = i >> 3, q = i & 7;
            uint32_t d = sw128((uint32_t)(r * 128 + q * 16));
            cp_async16(st + OFF_B_IN_STAGE + d, pb + (size_t)r * ROWB + q * 16);
        }
        cp_commit();
    };

    // warp layout: 4 (m) x 2 (n); warp tile 32 x 64
    const int wm = wid >> 1;
    const int wn = wid & 1;
    const int g  = lane >> 2;
    const int t4 = lane & 3;

    // ldmatrix lane address components (within 128B-row tile, before swizzle)
    const int a_row_off = lane & 15;
    const int a_k_off   = (lane >> 4) << 4;
    const int b_row_off = (lane & 7) + ((lane & 16) ? 8 : 0);
    const int b_k_off   = ((lane >> 3) & 1) << 4;

    float acc[2][8][4];
    #pragma unroll
    for (int im = 0; im < 2; im++)
        #pragma unroll
        for (int in = 0; in < 8; in++)
            #pragma unroll
            for (int r = 0; r < 4; r++) acc[im][in][r] = 0.f;

    issue(0);
    issue(1);

    for (int c = 0; c < NCHUNK; ++c) {
        if (c < NCHUNK - 2) cp_wait<1>();   // stage c resident (stage c+1 may fly)
        else                cp_wait<0>();
        __syncthreads();                    // one barrier per chunk
        if (c + 2 < NCHUNK) issue(c + 2);   // writes stage (c-1)%3, freed by the barrier

        const uint32_t aB = sb + (uint32_t)(c % NSTAGE) * STAGE_BYTES;
        const uint32_t bB = aB + OFF_B_IN_STAGE;

        // chunk = base-k 32: two k16 steps; hi at row bytes [0,64), lo at [64,128)
        #pragma unroll
        for (int ks = 0; ks < 2; ++ks) {
            const int kb = ks * 32;
            uint32_t ah[2][4], al[2][4];
            #pragma unroll
            for (int im = 0; im < 2; im++) {
                uint32_t rowb = (uint32_t)((wm * 32 + im * 16 + a_row_off) * 128);
                ldmatrix_x4(ah[im], aB + sw128(rowb + kb + a_k_off));
                ldmatrix_x4(al[im], aB + sw128(rowb + 64 + kb + a_k_off));
            }
            #pragma unroll
            for (int nb = 0; nb < 4; nb++) {
                uint32_t bh[4], bl[4];
                uint32_t rowb = (uint32_t)((wn * 64 + nb * 16 + b_row_off) * 128);
                ldmatrix_x4(bh, bB + sw128(rowb + kb + b_k_off));
                ldmatrix_x4(bl, bB + sw128(rowb + 64 + kb + b_k_off));
                #pragma unroll
                for (int im = 0; im < 2; im++) {
                    #pragma unroll
                    for (int half = 0; half < 2; half++) {
                        float* d = acc[im][nb * 2 + half];
                        mma16816(d, ah[im], bh + half * 2);   // hi*hi
                        mma16816(d, ah[im], bl + half * 2);   // hi*lo
                        mma16816(d, al[im], bh + half * 2);   // lo*hi
                    }
                }
            }
        }
    }

    // ---- stage quantiles + bias into (now dead) stage-0 smem ----
    __syncthreads();
    float* qs = (float*)(smem + OFF_QS);   // [128][33]
    float* bb = (float*)(smem + OFF_BB);   // [128]
    for (int i = tid; i < BN * NQ; i += 256) {
        int n = i / NQ, r = i - n * NQ;
        qs[n * 33 + r] = Q[(size_t)(bn + n) * NQ + r];
    }
    if (tid < BN) bb[tid] = bias[bn + tid];
    __syncthreads();

    // ---- epilogue: bias + searchsorted (levels 16/8 from regs), float2 stores
    #pragma unroll
    for (int in = 0; in < 8; in++) {
        const int col_l = wn * 64 + in * 8 + t4 * 2;
        const float* q0 = qs + col_l * 33;
        const float* q1 = q0 + 33;
        const float bz0 = bb[col_l], bz1 = bb[col_l + 1];
        const float q0p7 = q0[7], q0p15 = q0[15], q0p23 = q0[23];
        const float q1p7 = q1[7], q1p15 = q1[15], q1p23 = q1[23];
        #pragma unroll
        for (int im = 0; im < 2; im++) {
            #pragma unroll
            for (int half = 0; half < 2; half++) {
                const int row = bm + wm * 32 + im * 16 + g + half * 8;
                const float v0 = acc[im][in][half * 2];
                const float v1 = acc[im][in][half * 2 + 1];
                int p0 = 0, p1 = 0;
                // level 16 / 8 from registers
                float piv0, piv1;
                if (q0p15 < v0) p0 = 16;
                piv0 = (p0 == 16) ? q0p23 : q0p7;
                if (piv0 < v0) p0 += 8;
                if (q1p15 < v1) p1 = 16;
                piv1 = (p1 == 16) ? q1p23 : q1p7;
                if (piv1 < v1) p1 += 8;
                // levels 4 / 2 / 1 from smem (max index 30 < 31: no guards)
                if (q0[p0 + 3] < v0) p0 += 4;
                if (q0[p0 + 1] < v0) p0 += 2;
                if (q0[p0]     < v0) p0 += 1;
                if (q1[p1 + 3] < v1) p1 += 4;
                if (q1[p1 + 1] < v1) p1 += 2;
                if (q1[p1]     < v1) p1 += 1;
                const size_t off = (size_t)row * N_DIM + bn + col_l;
                *(float2*)(out  + off) = make_float2(v0 + bz0, v1 + bz1);
                *(float2*)(idxf + off) = make_float2((float)p0, (float)p1);
            }
        }
    }
}

// ================= launch =================
extern "C" void kernel_launch(void* const* d_in, const int* in_sizes, int n_in,
                              void* d_out, int out_size)
{
    const float* x    = (const float*)d_in[0];  // [16384, 256]
    const float* w    = (const float*)d_in[1];  // [4096, 256]
    const float* bias = (const float*)d_in[2];  // [4096]
    const float* q    = (const float*)d_in[3];  // [4096, 31]

    float* out  = (float*)d_out;
    float* idxf = out + (size_t)M_DIM * N_DIM;

    cudaFuncSetAttribute(gemm_kernel, cudaFuncAttributeMaxDynamicSharedMemorySize, SMEM_BYTES);

    convert_kernel<<<(M_DIM * K_DIM) / 256, 256>>>(x, w);
    dim3 grid(N_DIM / BN, M_DIM / BM);   // (32, 128) = 4096 blocks
    gemm_kernel<<<grid, 256, SMEM_BYTES>>>(bias, q, out, idxf);
}

// round 10
// speedup vs baseline: 1.2382x; 1.0037x over previous
#include <cuda_runtime.h>
#include <cuda_bf16.h>
#include <cstdint>

// Problem dims
#define M_DIM 16384
#define N_DIM 4096
#define K_DIM 256
#define NQ    31

// scratch layout: per row, K split into 8 blocks of 32 elems;
// each block stored as [hi x32 | lo x32]  -> row length 512 bf16 = 1024 B
#define KP    512
#define ROWB  1024       // bytes per scratch row

// GEMM tiling: CTA 128x128, 8 warps 4(m) x 2(n), warp tile 32x64
#define BM 128
#define BN 128
#define NCHUNK 8         // base-K chunks of 32 (each = 128 B/row hi+lo)
#define NSTAGE 3

__device__ __nv_bfloat16 g_Xp[(size_t)M_DIM * KP];   // 16 MB
__device__ __nv_bfloat16 g_Wp[(size_t)N_DIM * KP];   // 4 MB

// ---- dynamic smem layout (bytes) ----
#define STAGE_BYTES 32768
#define OFF_B_IN_STAGE 16384
#define SMEM_BYTES 98304
// epilogue overlays (main-loop buffers dead by then):
#define OFF_QS   0          // 128 cols x 33 f32 = 16896
#define OFF_BB   16896      // 128 f32 = 512

__device__ __forceinline__ uint32_t smem_u32(const void* p) {
    uint32_t a;
    asm("{ .reg .u64 t; cvta.to.shared.u64 t, %1; cvt.u32.u64 %0, t; }" : "=r"(a) : "l"(p));
    return a;
}
__device__ __forceinline__ uint32_t sw128(uint32_t off) {
    return off ^ ((off >> 3) & 0x70);
}
__device__ __forceinline__ void cp_async16(uint32_t dst, const void* src) {
    asm volatile("cp.async.cg.shared.global [%0], [%1], 16;" :: "r"(dst), "l"(src) : "memory");
}
__device__ __forceinline__ void cp_commit() {
    asm volatile("cp.async.commit_group;" ::: "memory");
}
template <int N>
__device__ __forceinline__ void cp_wait() {
    asm volatile("cp.async.wait_group %0;" :: "n"(N) : "memory");
}
__device__ __forceinline__ void ldmatrix_x4(uint32_t* r, uint32_t addr) {
    asm volatile("ldmatrix.sync.aligned.m8n8.x4.shared.b16 {%0,%1,%2,%3}, [%4];"
                 : "=r"(r[0]), "=r"(r[1]), "=r"(r[2]), "=r"(r[3]) : "r"(addr));
}
__device__ __forceinline__ void mma16816(float* d, const uint32_t* a, const uint32_t* b) {
    asm volatile(
        "mma.sync.aligned.m16n8k16.row.col.f32.bf16.bf16.f32 "
        "{%0,%1,%2,%3}, {%4,%5,%6,%7}, {%8,%9}, {%0,%1,%2,%3};"
        : "+f"(d[0]), "+f"(d[1]), "+f"(d[2]), "+f"(d[3])
        : "r"(a[0]), "r"(a[1]), "r"(a[2]), "r"(a[3]), "r"(b[0]), "r"(b[1]));
}

// ================= kernel 1: fp32 -> bf16 hi/lo (vectorized x4) =============
__global__ void __launch_bounds__(256)
convert_kernel(const float* __restrict__ X, const float* __restrict__ W)
{
    int i4 = (blockIdx.x * blockDim.x + threadIdx.x) * 4;   // covers M_DIM*K_DIM
    {
        float4 x = *(const float4*)(X + i4);
        float f[4] = {x.x, x.y, x.z, x.w};
        __nv_bfloat162 h2[2], l2[2];
        #pragma unroll
        for (int j = 0; j < 2; j++) {
            __nv_bfloat16 h0 = __float2bfloat16(f[j*2]);
            __nv_bfloat16 h1 = __float2bfloat16(f[j*2+1]);
            h2[j] = __nv_bfloat162(h0, h1);
            l2[j] = __nv_bfloat162(__float2bfloat16(f[j*2]   - __bfloat162float(h0)),
                                   __float2bfloat16(f[j*2+1] - __bfloat162float(h1)));
        }
        int m = i4 >> 8, k = i4 & 255;
        __nv_bfloat16* p = g_Xp + (size_t)m * KP + (k >> 5) * 64 + (k & 31);
        *(__nv_bfloat162*)(p)      = h2[0];
        *(__nv_bfloat162*)(p + 2)  = h2[1];
        *(__nv_bfloat162*)(p + 32) = l2[0];
        *(__nv_bfloat162*)(p + 34) = l2[1];
    }
    if (i4 < N_DIM * K_DIM) {
        float4 w = *(const float4*)(W + i4);
        float f[4] = {w.x, w.y, w.z, w.w};
        __nv_bfloat162 h2[2], l2[2];
        #pragma unroll
        for (int j = 0; j < 2; j++) {
            __nv_bfloat16 h0 = __float2bfloat16(f[j*2]);
            __nv_bfloat16 h1 = __float2bfloat16(f[j*2+1]);
            h2[j] = __nv_bfloat162(h0, h1);
            l2[j] = __nv_bfloat162(__float2bfloat16(f[j*2]   - __bfloat162float(h0)),
                                   __float2bfloat16(f[j*2+1] - __bfloat162float(h1)));
        }
        int n = i4 >> 8, k = i4 & 255;
        __nv_bfloat16* p = g_Wp + (size_t)n * KP + (k >> 5) * 64 + (k & 31);
        *(__nv_bfloat162*)(p)      = h2[0];
        *(__nv_bfloat162*)(p + 2)  = h2[1];
        *(__nv_bfloat162*)(p + 32) = l2[0];
        *(__nv_bfloat162*)(p + 34) = l2[1];
    }
}

// ================= kernel 2: HMMA GEMM + fused epilogue =================
extern __shared__ char smem[];

__global__ void __launch_bounds__(256, 2)
gemm_kernel(const float* __restrict__ bias, const float* __restrict__ Q,
            float* __restrict__ out, float* __restrict__ idxf)
{
    const int tid  = threadIdx.x;
    const int wid  = tid >> 5;
    const int lane = tid & 31;
    const int bm = blockIdx.y * BM;
    const int bn = blockIdx.x * BN;
    const uint32_t sb = smem_u32(smem);

    const char* gA = (const char*)g_Xp + (size_t)bm * ROWB;
    const char* gB = (const char*)g_Wp + (size_t)bn * ROWB;

    auto issue = [&](int c) {
        const uint32_t st = sb + (uint32_t)(c % NSTAGE) * STAGE_BYTES;
        const char* pa = gA + c * 128;
        const char* pb = gB + c * 128;
        #pragma unroll
        for (int t = 0; t < 4; ++t) {
            int i = tid + t * 256; int r = i >> 3, q = i & 7;
            uint32_t d = sw128((uint32_t)(r * 128 + q * 16));
            cp_async16(st + d, pa + (size_t)r * ROWB + q * 16);
        }
        #pragma unroll
        for (int t = 0; t < 4; ++t) {
            int i = tid + t * 256; int r = i >> 3, q = i & 7;
            uint32_t d = sw128((uint32_t)(r * 128 + q * 16));
            cp_async16(st + OFF_B_IN_STAGE + d, pb + (size_t)r * ROWB + q * 16);
        }
        cp_commit();
    };

    // warp layout: 4 (m) x 2 (n); warp tile 32 x 64
    const int wm = wid >> 1;
    const int wn = wid & 1;
    const int g  = lane >> 2;
    const int t4 = lane & 3;

    // ---- XOR-closed ldmatrix base offsets ----
    // sw128(row*128 + intra) = row*128 + (intra ^ ((row&7)<<4)); intra bits {16,32,64} disjoint
    uint32_t AOff[2], BOff[4];
    {
        const uint32_t a_k = (uint32_t)((lane >> 4) << 4);
        #pragma unroll
        for (int im = 0; im < 2; im++) {
            uint32_t row = (uint32_t)(wm * 32 + im * 16 + (lane & 15));
            AOff[im] = row * 128 + (((row & 7) << 4) ^ a_k);
        }
        const uint32_t b_k = (uint32_t)(((lane >> 3) & 1) << 4);
        #pragma unroll
        for (int nb = 0; nb < 4; nb++) {
            uint32_t row = (uint32_t)(wn * 64 + nb * 16 + (lane & 7) + ((lane & 16) ? 8 : 0));
            BOff[nb] = OFF_B_IN_STAGE + row * 128 + (((row & 7) << 4) ^ b_k);
        }
    }

    float acc[2][8][4];
    #pragma unroll
    for (int im = 0; im < 2; im++)
        #pragma unroll
        for (int in = 0; in < 8; in++)
            #pragma unroll
            for (int r = 0; r < 4; r++) acc[im][in][r] = 0.f;

    issue(0);
    issue(1);

    for (int c = 0; c < NCHUNK; ++c) {
        if (c < NCHUNK - 2) cp_wait<1>();
        else                cp_wait<0>();
        __syncthreads();
        if (c + 2 < NCHUNK) issue(c + 2);

        const uint32_t st = sb + (uint32_t)(c % NSTAGE) * STAGE_BYTES;
        const uint32_t a0 = st + AOff[0], a1 = st + AOff[1];
        uint32_t bbase[4];
        #pragma unroll
        for (int nb = 0; nb < 4; nb++) bbase[nb] = st + BOff[nb];

        // hoist ALL A fragments for the chunk: both ks, hi+lo (8 ldmatrix, MLP 8)
        uint32_t AH[2][2][4], AL[2][2][4];       // [ks][im][4]
        ldmatrix_x4(AH[0][0], a0);
        ldmatrix_x4(AL[0][0], a0 ^ 64u);
        ldmatrix_x4(AH[0][1], a1);
        ldmatrix_x4(AL[0][1], a1 ^ 64u);
        ldmatrix_x4(AH[1][0], a0 ^ 32u);
        ldmatrix_x4(AL[1][0], a0 ^ 96u);
        ldmatrix_x4(AH[1][1], a1 ^ 32u);
        ldmatrix_x4(AL[1][1], a1 ^ 96u);

        #pragma unroll
        for (int ks = 0; ks < 2; ++ks) {
            const uint32_t kx = ks ? 32u : 0u;
            #pragma unroll
            for (int nb = 0; nb < 4; nb++) {
                uint32_t bh[4], bl[4];
                ldmatrix_x4(bh, bbase[nb] ^ kx);
                ldmatrix_x4(bl, bbase[nb] ^ (kx | 64u));
                #pragma unroll
                for (int im = 0; im < 2; im++) {
                    #pragma unroll
                    for (int half = 0; half < 2; half++) {
                        float* d = acc[im][nb * 2 + half];
                        mma16816(d, AH[ks][im], bh + half * 2);   // hi*hi
                        mma16816(d, AH[ks][im], bl + half * 2);   // hi*lo
                        mma16816(d, AL[ks][im], bh + half * 2);   // lo*hi
                    }
                }
            }
        }
    }

    // ---- stage quantiles + bias into (now dead) stage-0 smem ----
    __syncthreads();
    float* qs = (float*)(smem + OFF_QS);   // [128][33]
    float* bb = (float*)(smem + OFF_BB);   // [128]
    for (int i = tid; i < BN * NQ; i += 256) {
        int n = i / NQ, r = i - n * NQ;
        qs[n * 33 + r] = Q[(size_t)(bn + n) * NQ + r];
    }
    if (tid < BN) bb[tid] = bias[bn + tid];
    __syncthreads();

    // ---- epilogue: bias + searchsorted (levels 16/8 from regs), float2 stores
    #pragma unroll
    for (int in = 0; in < 8; in++) {
        const int col_l = wn * 64 + in * 8 + t4 * 2;
        const float* q0 = qs + col_l * 33;
        const float* q1 = q0 + 33;
        const float bz0 = bb[col_l], bz1 = bb[col_l + 1];
        const float q0p7 = q0[7], q0p15 = q0[15], q0p23 = q0[23];
        const float q1p7 = q1[7], q1p15 = q1[15], q1p23 = q1[23];
        #pragma unroll
        for (int im = 0; im < 2; im++) {
            #pragma unroll
            for (int half = 0; half < 2; half++) {
                const int row = bm + wm * 32 + im * 16 + g + half * 8;
                const float v0 = acc[im][in][half * 2];
                const float v1 = acc[im][in][half * 2 + 1];
                int p0 = 0, p1 = 0;
                float piv0, piv1;
                if (q0p15 < v0) p0 = 16;
                piv0 = (p0 == 16) ? q0p23 : q0p7;
                if (piv0 < v0) p0 += 8;
                if (q1p15 < v1) p1 = 16;
                piv1 = (p1 == 16) ? q1p23 : q1p7;
                if (piv1 < v1) p1 += 8;
                if (q0[p0 + 3] < v0) p0 += 4;
                if (q0[p0 + 1] < v0) p0 += 2;
                if (q0[p0]     < v0) p0 += 1;
                if (q1[p1 + 3] < v1) p1 += 4;
                if (q1[p1 + 1] < v1) p1 += 2;
                if (q1[p1]     < v1) p1 += 1;
                const size_t off = (size_t)row * N_DIM + bn + col_l;
                *(float2*)(out  + off) = make_float2(v0 + bz0, v1 + bz1);
                *(float2*)(idxf + off) = make_float2((float)p0, (float)p1);
            }
        }
    }
}

// ================= launch =================
extern "C" void kernel_launch(void* const* d_in, const int* in_sizes, int n_in,
                              void* d_out, int out_size)
{
    const float* x    = (const float*)d_in[0];  // [16384, 256]
    const float* w    = (const float*)d_in[1];  // [4096, 256]
    const float* bias = (const float*)d_in[2];  // [4096]
    const float* q    = (const float*)d_in[3];  // [4096, 31]

    float* out  = (float*)d_out;
    float* idxf = out + (size_t)M_DIM * N_DIM;

    cudaFuncSetAttribute(gemm_kernel, cudaFuncAttributeMaxDynamicSharedMemorySize, SMEM_BYTES);

    convert_kernel<<<(M_DIM * K_DIM) / 1024, 256>>>(x, w);
    dim3 grid(N_DIM / BN, M_DIM / BM);   // (32, 128) = 4096 blocks
    gemm_kernel<<<grid, 256, SMEM_BYTES>>>(bias, q, out, idxf);
}

// round 12
// speedup vs baseline: 1.2489x; 1.0087x over previous
#include <cuda_runtime.h>
#include <cuda_bf16.h>
#include <cstdint>

// Problem dims
#define M_DIM 16384
#define N_DIM 4096
#define K_DIM 256
#define NQ    31

// Fragment-layout scratch:
//   [rowblk 16][kblk 16] blocks of 512B = 32 lanes x 16B (one MMA operand per lane)
//   kblk = c*4 + h*2 + sub   (c = base-k chunk of 32, h: 0=hi 1=lo, sub: k16 within chunk)
// X': 1024 mblk x 32 kblk;  W': 256 nblk x 32 kblk
__device__ uint4 g_Xf[1024 * 32 * 32];   // 16 MB
__device__ uint4 g_Wf[256 * 32 * 32];    // 4 MB

// GEMM tiling: CTA 128x128, 8 warps 4(m) x 2(n), warp tile 32x64
#define BM 128
#define BN 128
#define NCHUNK 8

__device__ __forceinline__ void ldg128(uint32_t* r, const uint4* p) {
    asm volatile("ld.global.nc.v4.u32 {%0,%1,%2,%3}, [%4];"
                 : "=r"(r[0]), "=r"(r[1]), "=r"(r[2]), "=r"(r[3]) : "l"(p));
}
__device__ __forceinline__ void mma16816(float* d, const uint32_t* a, const uint32_t* b) {
    asm volatile(
        "mma.sync.aligned.m16n8k16.row.col.f32.bf16.bf16.f32 "
        "{%0,%1,%2,%3}, {%4,%5,%6,%7}, {%8,%9}, {%0,%1,%2,%3};"
        : "+f"(d[0]), "+f"(d[1]), "+f"(d[2]), "+f"(d[3])
        : "r"(a[0]), "r"(a[1]), "r"(a[2]), "r"(a[3]), "r"(b[0]), "r"(b[1]));
}
__device__ __forceinline__ void split2(float2 v, uint32_t& hi, uint32_t& lo) {
    __nv_bfloat16 h0 = __float2bfloat16(v.x);
    __nv_bfloat16 h1 = __float2bfloat16(v.y);
    __nv_bfloat162 H(h0, h1);
    __nv_bfloat162 L(__float2bfloat16(v.x - __bfloat162float(h0)),
                     __float2bfloat16(v.y - __bfloat162float(h1)));
    hi = *(uint32_t*)&H;
    lo = *(uint32_t*)&L;
}

// ============ kernel 1: fp32 -> bf16 hi/lo, packed in MMA fragment order =====
// thread = (blk, c, sub, lane); produces the hi block lane and the lo block lane.
// A-reg order : r0=(g,c0) r1=(g+8,c0) r2=(g,c0+8) r3=(g+8,c0+8)
// B-reg order : r0=(g,c0) r1=(g,c0+8) r2=(g+8,c0) r3=(g+8,c0+8)
__global__ void __launch_bounds__(256)
convert_kernel(const float* __restrict__ X, const float* __restrict__ W)
{
    int t = blockIdx.x * blockDim.x + threadIdx.x;   // 655360 total
    const int lane = t & 31;
    const int g  = lane >> 2;
    const int c0 = (lane & 3) * 2;
    int rest = t >> 5;
    const int sub = rest & 1;
    const int c   = (rest >> 1) & 7;
    int blk = rest >> 4;
    const bool isX = blk < 1024;
    const float* src;
    if (isX) {
        src = X + (size_t)(blk * 16 + g) * K_DIM + c * 32 + sub * 16 + c0;
    } else {
        blk -= 1024;
        src = W + (size_t)(blk * 16 + g) * K_DIM + c * 32 + sub * 16 + c0;
    }
    float2 v0 = *(const float2*)(src);                // (g,     c0)
    float2 v2 = *(const float2*)(src + 8);            // (g,     c0+8)
    float2 v1 = *(const float2*)(src + 8 * K_DIM);    // (g+8,   c0)
    float2 v3 = *(const float2*)(src + 8 * K_DIM + 8);// (g+8,   c0+8)

    uint32_t h0, l0, h1, l1, h2, l2, h3, l3;
    split2(v0, h0, l0); split2(v1, h1, l1);
    split2(v2, h2, l2); split2(v3, h3, l3);

    uint4 qh, ql;
    if (isX) { qh = make_uint4(h0, h1, h2, h3); ql = make_uint4(l0, l1, l2, l3); }
    else     { qh = make_uint4(h0, h2, h1, h3); ql = make_uint4(l0, l2, l1, l3); }

    uint4* dst = (isX ? g_Xf : g_Wf) + ((size_t)blk * 32 + c * 4 + sub) * 32 + lane;
    dst[0]      = qh;          // hi : kblk c*4 + sub
    dst[2 * 32] = ql;          // lo : kblk c*4 + 2 + sub
}

// ============ kernel 2: barrier-free HMMA GEMM + fused epilogue ==============
__global__ void __launch_bounds__(256, 2)
gemm_kernel(const float* __restrict__ bias, const float* __restrict__ Q,
            float* __restrict__ out, float* __restrict__ idxf)
{
    __shared__ float qs[BN * 33];   // quantiles, stride-33 pad
    __shared__ float bb[BN];

    const int tid  = threadIdx.x;
    const int wid  = tid >> 5;
    const int lane = tid & 31;
    const int bm = blockIdx.y * BM;
    const int bn = blockIdx.x * BN;

    const int wm = wid >> 1;        // 0..3
    const int wn = wid & 1;         // 0..1
    const int g  = lane >> 2;
    const int t4 = lane & 3;

    // fragment stream pointers: index = (blk*32 + kblk)*32 + lane
    const uint4* pA0 = g_Xf + ((size_t)(bm >> 4) + wm * 2) * 1024 + lane;
    const uint4* pA1 = pA0 + 1024;
    const uint4* pB0 = g_Wf + ((size_t)(bn >> 4) + wn * 4) * 1024 + lane;
    const uint4* pB1 = pB0 + 1024;
    const uint4* pB2 = pB1 + 1024;
    const uint4* pB3 = pB2 + 1024;

    float acc[2][8][4];
    #pragma unroll
    for (int im = 0; im < 2; im++)
        #pragma unroll
        for (int in = 0; in < 8; in++)
            #pragma unroll
            for (int r = 0; r < 4; r++) acc[im][in][r] = 0.f;

    for (int c = 0; c < NCHUNK; ++c) {
        // A fragments for the whole chunk: [im][sub], hi and lo (8 LDG, MLP 8)
        uint32_t AH[2][2][4], AL[2][2][4];
        ldg128(AH[0][0], pA0);      ldg128(AH[0][1], pA0 + 32);
        ldg128(AL[0][0], pA0 + 64); ldg128(AL[0][1], pA0 + 96);
        ldg128(AH[1][0], pA1);      ldg128(AH[1][1], pA1 + 32);
        ldg128(AL[1][0], pA1 + 64); ldg128(AL[1][1], pA1 + 96);

        const uint4* pB[4] = {pB0, pB1, pB2, pB3};
        #pragma unroll
        for (int nb = 0; nb < 4; nb++) {
            uint32_t BH0[4], BH1[4], BL0[4], BL1[4];
            ldg128(BH0, pB[nb]);
            ldg128(BH1, pB[nb] + 32);
            ldg128(BL0, pB[nb] + 64);
            ldg128(BL1, pB[nb] + 96);
            #pragma unroll
            for (int im = 0; im < 2; im++) {
                #pragma unroll
                for (int half = 0; half < 2; half++) {
                    float* d = acc[im][nb * 2 + half];
                    mma16816(d, AH[im][0], BH0 + half * 2);   // hi*hi  sub0
                    mma16816(d, AH[im][0], BL0 + half * 2);   // hi*lo
                    mma16816(d, AL[im][0], BH0 + half * 2);   // lo*hi
                    mma16816(d, AH[im][1], BH1 + half * 2);   // hi*hi  sub1
                    mma16816(d, AH[im][1], BL1 + half * 2);   // hi*lo
                    mma16816(d, AL[im][1], BH1 + half * 2);   // lo*hi
                }
            }
        }
        pA0 += 128; pA1 += 128;
        pB0 += 128; pB1 += 128; pB2 += 128; pB3 += 128;
    }

    // ---- stage quantiles + bias ----
    for (int i = tid; i < BN * NQ; i += 256) {
        int n = i / NQ, r = i - n * NQ;
        qs[n * 33 + r] = Q[(size_t)(bn + n) * NQ + r];
    }
    if (tid < BN) bb[tid] = bias[bn + tid];
    __syncthreads();

    // ---- epilogue: bias + searchsorted (levels 16/8 from regs), float2 stores
    #pragma unroll
    for (int in = 0; in < 8; in++) {
        const int col_l = wn * 64 + in * 8 + t4 * 2;
        const float* q0 = qs + col_l * 33;
        const float* q1 = q0 + 33;
        const float bz0 = bb[col_l], bz1 = bb[col_l + 1];
        const float q0p7 = q0[7], q0p15 = q0[15], q0p23 = q0[23];
        const float q1p7 = q1[7], q1p15 = q1[15], q1p23 = q1[23];
        #pragma unroll
        for (int im = 0; im < 2; im++) {
            #pragma unroll
            for (int half = 0; half < 2; half++) {
                const int row = bm + wm * 32 + im * 16 + g + half * 8;
                const float v0 = acc[im][in][half * 2];
                const float v1 = acc[im][in][half * 2 + 1];
                int p0 = 0, p1 = 0;
                float piv0, piv1;
                if (q0p15 < v0) p0 = 16;
                piv0 = (p0 == 16) ? q0p23 : q0p7;
                if (piv0 < v0) p0 += 8;
                if (q1p15 < v1) p1 = 16;
                piv1 = (p1 == 16) ? q1p23 : q1p7;
                if (piv1 < v1) p1 += 8;
                if (q0[p0 + 3] < v0) p0 += 4;
                if (q0[p0 + 1] < v0) p0 += 2;
                if (q0[p0]     < v0) p0 += 1;
                if (q1[p1 + 3] < v1) p1 += 4;
                if (q1[p1 + 1] < v1) p1 += 2;
                if (q1[p1]     < v1) p1 += 1;
                const size_t off = (size_t)row * N_DIM + bn + col_l;
                *(float2*)(out  + off) = make_float2(v0 + bz0, v1 + bz1);
                *(float2*)(idxf + off) = make_float2((float)p0, (float)p1);
            }
        }
    }
}

// ================= launch =================
extern "C" void kernel_launch(void* const* d_in, const int* in_sizes, int n_in,
                              void* d_out, int out_size)
{
    const float* x    = (const float*)d_in[0];  // [16384, 256]
    const float* w    = (const float*)d_in[1];  // [4096, 256]
    const float* bias = (const float*)d_in[2];  // [4096]
    const float* q    = (const float*)d_in[3];  // [4096, 31]

    float* out  = (float*)d_out;
    float* idxf = out + (size_t)M_DIM * N_DIM;

    // X: 1024 mblk * 512 thr + W: 256 nblk * 512 thr = 655360 threads
    convert_kernel<<<655360 / 256, 256>>>(x, w);
    dim3 grid(N_DIM / BN, M_DIM / BM);   // (32, 128) = 4096 blocks
    gemm_kernel<<<grid, 256>>>(bias, q, out, idxf);
}

// round 13
// speedup vs baseline: 1.5065x; 1.2063x over previous
#include <cuda_runtime.h>
#include <cuda_fp16.h>
#include <cstdint>

// Problem dims
#define M_DIM 16384
#define N_DIM 4096
#define K_DIM 256
#define NQ    31

// Fragment-layout scratch (one MMA operand per lane, 512B blocks = 32 lanes x 16B)
// X': [mblk 1024][kblk 32]  kblk = c*4 + h*2 + sub   (h: 0=hi 1=lo)   16 MB fp16
// W': [nblk 256][kblk 16]   kblk = c*2 + sub         (single fp16)     2 MB
__device__ uint4 g_Xf[1024 * 32 * 32];
__device__ uint4 g_Wf[256 * 16 * 32];

// GEMM tiling: CTA 128x128, 8 warps 4(m) x 2(n), warp tile 32x64
#define BM 128
#define BN 128
#define NCHUNK 8

__device__ __forceinline__ void ldg128(uint32_t* r, const uint4* p) {
    asm volatile("ld.global.nc.v4.u32 {%0,%1,%2,%3}, [%4];"
                 : "=r"(r[0]), "=r"(r[1]), "=r"(r[2]), "=r"(r[3]) : "l"(p));
}
__device__ __forceinline__ void mma16816(float* d, const uint32_t* a, const uint32_t* b) {
    asm volatile(
        "mma.sync.aligned.m16n8k16.row.col.f32.f16.f16.f32 "
        "{%0,%1,%2,%3}, {%4,%5,%6,%7}, {%8,%9}, {%0,%1,%2,%3};"
        : "+f"(d[0]), "+f"(d[1]), "+f"(d[2]), "+f"(d[3])
        : "r"(a[0]), "r"(a[1]), "r"(a[2]), "r"(a[3]), "r"(b[0]), "r"(b[1]));
}
__device__ __forceinline__ void splitx2(float2 v, uint32_t& hi, uint32_t& lo) {
    __half h0 = __float2half_rn(v.x);
    __half h1 = __float2half_rn(v.y);
    __half2 H(h0, h1);
    __half2 L(__float2half_rn(v.x - __half2float(h0)),
              __float2half_rn(v.y - __half2float(h1)));
    hi = *(uint32_t*)&H;
    lo = *(uint32_t*)&L;
}
__device__ __forceinline__ uint32_t pack2(float2 v) {
    __half2 H(__float2half_rn(v.x), __float2half_rn(v.y));
    return *(uint32_t*)&H;
}

// ============ kernel 1: fp32 -> fp16 fragments =====
// A-reg order : r0=(g,c0) r1=(g+8,c0) r2=(g,c0+8) r3=(g+8,c0+8)
// B-reg order : r0=(g,c0) r1=(g,c0+8) r2=(g+8,c0) r3=(g+8,c0+8)
__global__ void __launch_bounds__(256)
convert_kernel(const float* __restrict__ X, const float* __restrict__ W)
{
    int t = blockIdx.x * blockDim.x + threadIdx.x;   // 655360 total
    const int lane = t & 31;
    const int g  = lane >> 2;
    const int c0 = (lane & 3) * 2;
    int rest = t >> 5;
    const int sub = rest & 1;
    const int c   = (rest >> 1) & 7;
    int blk = rest >> 4;

    if (blk < 1024) {   // X: hi + lo
        const float* src = X + (size_t)(blk * 16 + g) * K_DIM + c * 32 + sub * 16 + c0;
        float2 v0 = *(const float2*)(src);
        float2 v2 = *(const float2*)(src + 8);
        float2 v1 = *(const float2*)(src + 8 * K_DIM);
        float2 v3 = *(const float2*)(src + 8 * K_DIM + 8);
        uint32_t h0, l0, h1, l1, h2, l2, h3, l3;
        splitx2(v0, h0, l0); splitx2(v1, h1, l1);
        splitx2(v2, h2, l2); splitx2(v3, h3, l3);
        uint4* dst = g_Xf + ((size_t)blk * 32 + c * 4 + sub) * 32 + lane;
        dst[0]      = make_uint4(h0, h1, h2, h3);   // hi
        dst[2 * 32] = make_uint4(l0, l1, l2, l3);   // lo
    } else {            // W: single fp16
        blk -= 1024;
        const float* src = W + (size_t)(blk * 16 + g) * K_DIM + c * 32 + sub * 16 + c0;
        float2 v0 = *(const float2*)(src);
        float2 v2 = *(const float2*)(src + 8);
        float2 v1 = *(const float2*)(src + 8 * K_DIM);
        float2 v3 = *(const float2*)(src + 8 * K_DIM + 8);
        uint4* dst = g_Wf + ((size_t)blk * 16 + c * 2 + sub) * 32 + lane;
        dst[0] = make_uint4(pack2(v0), pack2(v2), pack2(v1), pack2(v3));
    }
}

// ============ kernel 2: barrier-free HMMA GEMM + fused epilogue ==============
__global__ void __launch_bounds__(256, 2)
gemm_kernel(const float* __restrict__ bias, const float* __restrict__ Q,
            float* __restrict__ out, float* __restrict__ idxf)
{
    __shared__ float qs[BN * 33];
    __shared__ float bb[BN];

    const int tid  = threadIdx.x;
    const int wid  = tid >> 5;
    const int lane = tid & 31;
    const int bm = blockIdx.y * BM;
    const int bn = blockIdx.x * BN;

    const int wm = wid >> 1;
    const int wn = wid & 1;
    const int g  = lane >> 2;
    const int t4 = lane & 3;

    // A stream: blk stride 32 kblk * 32 = 1024; B stream: blk stride 16*32 = 512
    const uint4* pA0 = g_Xf + ((size_t)(bm >> 4) + wm * 2) * 1024 + lane;
    const uint4* pA1 = pA0 + 1024;
    const uint4* pB0 = g_Wf + ((size_t)(bn >> 4) + wn * 4) * 512 + lane;
    const uint4* pB1 = pB0 + 512;
    const uint4* pB2 = pB1 + 512;
    const uint4* pB3 = pB2 + 512;

    float acc[2][8][4];
    #pragma unroll
    for (int im = 0; im < 2; im++)
        #pragma unroll
        for (int in = 0; in < 8; in++)
            #pragma unroll
            for (int r = 0; r < 4; r++) acc[im][in][r] = 0.f;

    for (int c = 0; c < NCHUNK; ++c) {
        // A fragments for the chunk: [im][sub], hi and lo (8 LDG, MLP 8)
        uint32_t AH[2][2][4], AL[2][2][4];
        ldg128(AH[0][0], pA0);      ldg128(AH[0][1], pA0 + 32);
        ldg128(AL[0][0], pA0 + 64); ldg128(AL[0][1], pA0 + 96);
        ldg128(AH[1][0], pA1);      ldg128(AH[1][1], pA1 + 32);
        ldg128(AL[1][0], pA1 + 64); ldg128(AL[1][1], pA1 + 96);

        const uint4* pB[4] = {pB0, pB1, pB2, pB3};
        #pragma unroll
        for (int nb = 0; nb < 4; nb++) {
            uint32_t B0[4], B1[4];                    // sub0, sub1
            ldg128(B0, pB[nb]);
            ldg128(B1, pB[nb] + 32);
            #pragma unroll
            for (int im = 0; im < 2; im++) {
                #pragma unroll
                for (int half = 0; half < 2; half++) {
                    float* d = acc[im][nb * 2 + half];
                    mma16816(d, AH[im][0], B0 + half * 2);   // hi  sub0
                    mma16816(d, AL[im][0], B0 + half * 2);   // lo  sub0
                    mma16816(d, AH[im][1], B1 + half * 2);   // hi  sub1
                    mma16816(d, AL[im][1], B1 + half * 2);   // lo  sub1
                }
            }
        }
        pA0 += 128; pA1 += 128;
        pB0 += 64;  pB1 += 64; pB2 += 64; pB3 += 64;
    }

    // ---- stage quantiles + bias ----
    for (int i = tid; i < BN * NQ; i += 256) {
        int n = i / NQ, r = i - n * NQ;
        qs[n * 33 + r] = Q[(size_t)(bn + n) * NQ + r];
    }
    if (tid < BN) bb[tid] = bias[bn + tid];
    __syncthreads();

    // ---- epilogue: bias + searchsorted (levels 16/8 from regs), float2 stores
    #pragma unroll
    for (int in = 0; in < 8; in++) {
        const int col_l = wn * 64 + in * 8 + t4 * 2;
        const float* q0 = qs + col_l * 33;
        const float* q1 = q0 + 33;
        const float bz0 = bb[col_l], bz1 = bb[col_l + 1];
        const float q0p7 = q0[7], q0p15 = q0[15], q0p23 = q0[23];
        const float q1p7 = q1[7], q1p15 = q1[15], q1p23 = q1[23];
        #pragma unroll
        for (int im = 0; im < 2; im++) {
            #pragma unroll
            for (int half = 0; half < 2; half++) {
                const int row = bm + wm * 32 + im * 16 + g + half * 8;
                const float v0 = acc[im][in][half * 2];
                const float v1 = acc[im][in][half * 2 + 1];
                int p0 = 0, p1 = 0;
                float piv0, piv1;
                if (q0p15 < v0) p0 = 16;
                piv0 = (p0 == 16) ? q0p23 : q0p7;
                if (piv0 < v0) p0 += 8;
                if (q1p15 < v1) p1 = 16;
                piv1 = (p1 == 16) ? q1p23 : q1p7;
                if (piv1 < v1) p1 += 8;
                if (q0[p0 + 3] < v0) p0 += 4;
                if (q0[p0 + 1] < v0) p0 += 2;
                if (q0[p0]     < v0) p0 += 1;
                if (q1[p1 + 3] < v1) p1 += 4;
                if (q1[p1 + 1] < v1) p1 += 2;
                if (q1[p1]     < v1) p1 += 1;
                const size_t off = (size_t)row * N_DIM + bn + col_l;
                *(float2*)(out  + off) = make_float2(v0 + bz0, v1 + bz1);
                *(float2*)(idxf + off) = make_float2((float)p0, (float)p1);
            }
        }
    }
}

// ================= launch =================
extern "C" void kernel_launch(void* const* d_in, const int* in_sizes, int n_in,
                              void* d_out, int out_size)
{
    const float* x    = (const float*)d_in[0];  // [16384, 256]
    const float* w    = (const float*)d_in[1];  // [4096, 256]
    const float* bias = (const float*)d_in[2];  // [4096]
    const float* q    = (const float*)d_in[3];  // [4096, 31]

    float* out  = (float*)d_out;
    float* idxf = out + (size_t)M_DIM * N_DIM;

    convert_kernel<<<655360 / 256, 256>>>(x, w);
    dim3 grid(N_DIM / BN, M_DIM / BM);   // (32, 128) = 4096 blocks
    gemm_kernel<<<grid, 256>>>(bias, q, out, idxf);
}

// round 15
// speedup vs baseline: 1.5217x; 1.0101x over previous
#include <cuda_runtime.h>
#include <cuda_fp16.h>
#include <cstdint>

// Problem dims
#define M_DIM 16384
#define N_DIM 4096
#define K_DIM 256
#define NQ    31

// Fragment-layout scratch (one MMA operand per lane, 512B blocks = 32 lanes x 16B)
// X': [mblk 1024][kblk 32]  kblk = c*4 + h*2 + sub   (h: 0=hi 1=lo)   16 MB fp16
// W': [nblk 256][kblk 16]   kblk = c*2 + sub         (single fp16)     2 MB
__device__ uint4 g_Xf[1024 * 32 * 32];
__device__ uint4 g_Wf[256 * 16 * 32];

// GEMM tiling: CTA 128x128, 8 warps 4(m) x 2(n), warp tile 32x64
#define BM 128
#define BN 128
#define NCHUNK 8

__device__ __forceinline__ void ldg128(uint32_t* r, const uint4* p) {
    asm volatile("ld.global.nc.v4.u32 {%0,%1,%2,%3}, [%4];"
                 : "=r"(r[0]), "=r"(r[1]), "=r"(r[2]), "=r"(r[3]) : "l"(p));
}
__device__ __forceinline__ void mma16816(float* d, const uint32_t* a, const uint32_t* b) {
    asm volatile(
        "mma.sync.aligned.m16n8k16.row.col.f32.f16.f16.f32 "
        "{%0,%1,%2,%3}, {%4,%5,%6,%7}, {%8,%9}, {%0,%1,%2,%3};"
        : "+f"(d[0]), "+f"(d[1]), "+f"(d[2]), "+f"(d[3])
        : "r"(a[0]), "r"(a[1]), "r"(a[2]), "r"(a[3]), "r"(b[0]), "r"(b[1]));
}
__device__ __forceinline__ void splitx2(float2 v, uint32_t& hi, uint32_t& lo) {
    __half h0 = __float2half_rn(v.x);
    __half h1 = __float2half_rn(v.y);
    __half2 H(h0, h1);
    __half2 L(__float2half_rn(v.x - __half2float(h0)),
              __float2half_rn(v.y - __half2float(h1)));
    hi = *(uint32_t*)&H;
    lo = *(uint32_t*)&L;
}
__device__ __forceinline__ uint32_t pack2(float2 v) {
    __half2 H(__float2half_rn(v.x), __float2half_rn(v.y));
    return *(uint32_t*)&H;
}

// ============ kernel 1: fp32 -> fp16 fragments =====
// A-reg order : r0=(g,c0) r1=(g+8,c0) r2=(g,c0+8) r3=(g+8,c0+8)
// B-reg order : r0=(g,c0) r1=(g,c0+8) r2=(g+8,c0) r3=(g+8,c0+8)
__global__ void __launch_bounds__(256)
convert_kernel(const float* __restrict__ X, const float* __restrict__ W)
{
    int t = blockIdx.x * blockDim.x + threadIdx.x;   // 655360 total
    const int lane = t & 31;
    const int g  = lane >> 2;
    const int c0 = (lane & 3) * 2;
    int rest = t >> 5;
    const int sub = rest & 1;
    const int c   = (rest >> 1) & 7;
    int blk = rest >> 4;

    if (blk < 1024) {   // X: hi + lo
        const float* src = X + (size_t)(blk * 16 + g) * K_DIM + c * 32 + sub * 16 + c0;
        float2 v0 = *(const float2*)(src);
        float2 v2 = *(const float2*)(src + 8);
        float2 v1 = *(const float2*)(src + 8 * K_DIM);
        float2 v3 = *(const float2*)(src + 8 * K_DIM + 8);
        uint32_t h0, l0, h1, l1, h2, l2, h3, l3;
        splitx2(v0, h0, l0); splitx2(v1, h1, l1);
        splitx2(v2, h2, l2); splitx2(v3, h3, l3);
        uint4* dst = g_Xf + ((size_t)blk * 32 + c * 4 + sub) * 32 + lane;
        dst[0]      = make_uint4(h0, h1, h2, h3);   // hi
        dst[2 * 32] = make_uint4(l0, l1, l2, l3);   // lo
    } else {            // W: single fp16
        blk -= 1024;
        const float* src = W + (size_t)(blk * 16 + g) * K_DIM + c * 32 + sub * 16 + c0;
        float2 v0 = *(const float2*)(src);
        float2 v2 = *(const float2*)(src + 8);
        float2 v1 = *(const float2*)(src + 8 * K_DIM);
        float2 v3 = *(const float2*)(src + 8 * K_DIM + 8);
        uint4* dst = g_Wf + ((size_t)blk * 16 + c * 2 + sub) * 32 + lane;
        dst[0] = make_uint4(pack2(v0), pack2(v2), pack2(v1), pack2(v3));
    }
}

// ============ kernel 2: barrier-free pipelined HMMA GEMM + fused epilogue ====
__global__ void __launch_bounds__(256, 2)
gemm_kernel(const float* __restrict__ bias, const float* __restrict__ Q,
            float* __restrict__ out, float* __restrict__ idxf)
{
    __shared__ float qs[BN * 33];
    __shared__ float bb[BN];

    const int tid  = threadIdx.x;
    const int wid  = tid >> 5;
    const int lane = tid & 31;
    const int bm = blockIdx.y * BM;
    const int bn = blockIdx.x * BN;

    const int wm = wid >> 1;
    const int wn = wid & 1;
    const int g  = lane >> 2;
    const int t4 = lane & 3;

    // A stream: mblk stride 32 kblk * 32 lanes = 1024; B stream: nblk stride 512
    const uint4* pA0 = g_Xf + ((size_t)(bm >> 4) + wm * 2) * 1024 + lane;
    const uint4* pA1 = pA0 + 1024;
    const uint4* pB0 = g_Wf + ((size_t)(bn >> 4) + wn * 4) * 512 + lane;
    const uint4* pB1 = pB0 + 512;
    const uint4* pB2 = pB1 + 512;
    const uint4* pB3 = pB2 + 512;

    float acc[2][8][4];
    #pragma unroll
    for (int im = 0; im < 2; im++)
        #pragma unroll
        for (int in = 0; in < 8; in++)
            #pragma unroll
            for (int r = 0; r < 4; r++) acc[im][in][r] = 0.f;

    // double-buffered per-sub A fragments: [h][im][frag]
    uint32_t A0[2][2][4], A1[2][2][4], B[4][4];

    // A offset for (c, sub, h): c*128 + h*64 + sub*32   (uint4 units)
#define LOAD_A(Abuf, off)                      \
    do {                                       \
        ldg128(Abuf[0][0], pA0 + (off));       \
        ldg128(Abuf[1][0], pA0 + (off) + 64);  \
        ldg128(Abuf[0][1], pA1 + (off));       \
        ldg128(Abuf[1][1], pA1 + (off) + 64);  \
    } while (0)

#define DO_MMAS(Abuf)                                            \
    do {                                                         \
        _Pragma("unroll")                                        \
        for (int nb = 0; nb < 4; nb++) {                         \
            _Pragma("unroll")                                    \
            for (int im = 0; im < 2; im++) {                     \
                _Pragma("unroll")                                \
                for (int half = 0; half < 2; half++) {           \
                    float* d = acc[im][nb * 2 + half];           \
                    mma16816(d, Abuf[0][im], B[nb] + half * 2);  \
                    mma16816(d, Abuf[1][im], B[nb] + half * 2);  \
                }                                                \
            }                                                    \
        }                                                        \
    } while (0)

    LOAD_A(A0, 0);                         // c=0, sub=0

    for (int c = 0; c < NCHUNK; ++c) {
        const int ca = c * 128;            // A chunk offset
        const int cb = c * 64;             // B chunk offset

        // ---- sub 0: consume A0, prefetch A1 (this chunk's sub 1) ----
        ldg128(B[0], pB0 + cb);
        ldg128(B[1], pB1 + cb);
        ldg128(B[2], pB2 + cb);
        ldg128(B[3], pB3 + cb);
        LOAD_A(A1, ca + 32);
        DO_MMAS(A0);

        // ---- sub 1: consume A1, prefetch A0 (next chunk's sub 0) ----
        ldg128(B[0], pB0 + cb + 32);
        ldg128(B[1], pB1 + cb + 32);
        ldg128(B[2], pB2 + cb + 32);
        ldg128(B[3], pB3 + cb + 32);
        if (c + 1 < NCHUNK) LOAD_A(A0, ca + 128);
        DO_MMAS(A1);
    }
#undef LOAD_A
#undef DO_MMAS

    // ---- stage quantiles + bias ----
    for (int i = tid; i < BN * NQ; i += 256) {
        int n = i / NQ, r = i - n * NQ;
        qs[n * 33 + r] = Q[(size_t)(bn + n) * NQ + r];
    }
    if (tid < BN) bb[tid] = bias[bn + tid];
    __syncthreads();

    // ---- epilogue: bias + searchsorted (levels 16/8 from regs), float2 stores
    #pragma unroll
    for (int in = 0; in < 8; in++) {
        const int col_l = wn * 64 + in * 8 + t4 * 2;
        const float* q0 = qs + col_l * 33;
        const float* q1 = q0 + 33;
        const float bz0 = bb[col_l], bz1 = bb[col_l + 1];
        const float q0p7 = q0[7], q0p15 = q0[15], q0p23 = q0[23];
        const float q1p7 = q1[7], q1p15 = q1[15], q1p23 = q1[23];
        #pragma unroll
        for (int im = 0; im < 2; im++) {
            #pragma unroll
            for (int half = 0; half < 2; half++) {
                const int row = bm + wm * 32 + im * 16 + g + half * 8;
                const float v0 = acc[im][in][half * 2];
                const float v1 = acc[im][in][half * 2 + 1];
                int p0 = 0, p1 = 0;
                float piv0, piv1;
                if (q0p15 < v0) p0 = 16;
                piv0 = (p0 == 16) ? q0p23 : q0p7;
                if (piv0 < v0) p0 += 8;
                if (q1p15 < v1) p1 = 16;
                piv1 = (p1 == 16) ? q1p23 : q1p7;
                if (piv1 < v1) p1 += 8;
                if (q0[p0 + 3] < v0) p0 += 4;
                if (q0[p0 + 1] < v0) p0 += 2;
                if (q0[p0]     < v0) p0 += 1;
                if (q1[p1 + 3] < v1) p1 += 4;
                if (q1[p1 + 1] < v1) p1 += 2;
                if (q1[p1]     < v1) p1 += 1;
                const size_t off = (size_t)row * N_DIM + bn + col_l;
                *(float2*)(out  + off) = make_float2(v0 + bz0, v1 + bz1);
                *(float2*)(idxf + off) = make_float2((float)p0, (float)p1);
            }
        }
    }
}

// ================= launch =================
extern "C" void kernel_launch(void* const* d_in, const int* in_sizes, int n_in,
                              void* d_out, int out_size)
{
    const float* x    = (const float*)d_in[0];  // [16384, 256]
    const float* w    = (const float*)d_in[1];  // [4096, 256]
    const float* bias = (const float*)d_in[2];  // [4096]
    const float* q    = (const float*)d_in[3];  // [4096, 31]

    float* out  = (float*)d_out;
    float* idxf = out + (size_t)M_DIM * N_DIM;

    convert_kernel<<<655360 / 256, 256>>>(x, w);
    dim3 grid(N_DIM / BN, M_DIM / BM);   // (32, 128) = 4096 blocks
    gemm_kernel<<<grid, 256>>>(bias, q, out, idxf);
}